// round 2
// baseline (speedup 1.0000x reference)
#include <cuda_runtime.h>
#include <math.h>

// Problem constants
#define BATCH 4
#define DPOS  3
#define MPAR  64
#define N2  512
#define N1  2048
#define N0  8192
#define C2  256
#define C1  128
#define C0  64

// Derived
#define NT1 (BATCH * N1)          // 8192 layer-1 targets
#define NT0 (BATCH * N0)          // 32768 layer-2 targets
#define KD1 (C2 + C1)             // 384
#define H1  256
#define O1  128
#define KD2 (O1 + C0)             // 192
#define H2  128
#define O2  64

// -------- scratch (device globals; no allocation allowed) --------
__device__ float g_xcat1[NT1 * KD1];     // layer-1 MLP input  (8192 x 384)
__device__ float g_x1   [NT1 * O1];      // layer-1 output     (8192 x 128)
__device__ float g_xcat2[NT0 * KD2];     // layer-2 MLP input  (32768 x 192)
__device__ int   g_idx1 [NT1 * 3];
__device__ float g_w1   [NT1 * 3];
__device__ int   g_idx2 [NT0 * 3];
__device__ float g_w2   [NT0 * 3];
__device__ float g_p0   [BATCH * O1];
__device__ float g_p1   [BATCH * O2];

__device__ __forceinline__ float ftanh(float x) {
    // tanh(x) = 1 - 2/(exp(2x)+1); exp via MUFU. |rel err| ~1e-6.
    float e = __expf(2.0f * x);
    return 1.0f - __fdividef(2.0f, e + 1.0f);
}

// -------- par branch: p0 = tanh(par @ Wp0 + bp0), p1 = tanh(par @ Wp1 + bp1) --------
__global__ void par_kernel(const float* __restrict__ par,
                           const float* __restrict__ Wp0, const float* __restrict__ bp0,
                           const float* __restrict__ Wp1, const float* __restrict__ bp1)
{
    int j = threadIdx.x;  // 0..127
    #pragma unroll
    for (int b = 0; b < BATCH; b++) {
        float a0 = 0.0f;
        #pragma unroll 8
        for (int m = 0; m < MPAR; m++)
            a0 = fmaf(par[b * MPAR + m], Wp0[m * O1 + j], a0);
        g_p0[b * O1 + j] = ftanh(a0 + bp0[j]);
        if (j < O2) {
            float a1 = 0.0f;
            #pragma unroll 8
            for (int m = 0; m < MPAR; m++)
                a1 = fmaf(par[b * MPAR + m], Wp1[m * O2 + j], a1);
            g_p1[b * O2 + j] = ftanh(a1 + bp1[j]);
        }
    }
}

// -------- KNN (k=3), thread-per-target, sources staged in shared --------
template<int LAYER>
__global__ __launch_bounds__(128) void knn_kernel(const float* __restrict__ pos_src,
                                                  const float* __restrict__ pos_tgt)
{
    constexpr int NS  = (LAYER == 1) ? N2 : N1;   // sources per batch
    constexpr int TPB = (LAYER == 1) ? N1 : N0;   // targets per batch
    constexpr int BLK = 128;
    __shared__ float sp[NS * 3];

    int* __restrict__ idx_out  = (LAYER == 1) ? g_idx1 : g_idx2;
    float* __restrict__ w_out  = (LAYER == 1) ? g_w1   : g_w2;

    const int bpb = TPB / BLK;                 // blocks per batch
    const int b   = blockIdx.x / bpb;
    const int t0  = (blockIdx.x % bpb) * BLK;
    const float* ps = pos_src + (size_t)b * NS * 3;
    for (int i = threadIdx.x; i < NS * 3; i += BLK) sp[i] = ps[i];
    __syncthreads();

    const int gt = b * TPB + t0 + threadIdx.x;
    const float px = pos_tgt[gt * 3 + 0];
    const float py = pos_tgt[gt * 3 + 1];
    const float pz = pos_tgt[gt * 3 + 2];

    float d0 = 3.4e38f, d1 = 3.4e38f, d2 = 3.4e38f;
    int   i0 = 0, i1 = 0, i2 = 0;

    #pragma unroll 4
    for (int s = 0; s < NS; s++) {
        float dx = px - sp[s * 3 + 0];
        float dy = py - sp[s * 3 + 1];
        float dz = pz - sp[s * 3 + 2];
        float d  = fmaf(dx, dx, fmaf(dy, dy, dz * dz));
        if (d < d2) {
            if (d < d1) {
                d2 = d1; i2 = i1;
                if (d < d0) { d1 = d0; i1 = i0; d0 = d; i0 = s; }
                else        { d1 = d;  i1 = s; }
            } else { d2 = d; i2 = s; }
        }
    }

    const int base = b * NS;
    idx_out[gt * 3 + 0] = base + i0;
    idx_out[gt * 3 + 1] = base + i1;
    idx_out[gt * 3 + 2] = base + i2;
    w_out[gt * 3 + 0] = __fdividef(1.0f, fmaxf(d0, 1e-16f));
    w_out[gt * 3 + 1] = __fdividef(1.0f, fmaxf(d1, 1e-16f));
    w_out[gt * 3 + 2] = __fdividef(1.0f, fmaxf(d2, 1e-16f));
}

// -------- interpolate + concat skip features, warp-per-target --------
template<int LAYER>
__global__ __launch_bounds__(128) void interp_concat_kernel(const float* __restrict__ xsrc_arg,
                                                            const float* __restrict__ xskip)
{
    constexpr int C  = (LAYER == 1) ? C2 : O1;    // 256 / 128
    constexpr int CS = (LAYER == 1) ? C1 : C0;    // 128 / 64
    constexpr int LD = C + CS;

    const float* __restrict__ xsrc = (LAYER == 1) ? xsrc_arg : g_x1;
    const int*   __restrict__ idx  = (LAYER == 1) ? g_idx1 : g_idx2;
    const float* __restrict__ w    = (LAYER == 1) ? g_w1   : g_w2;
    float*       __restrict__ out  = (LAYER == 1) ? g_xcat1 : g_xcat2;

    const int t    = (blockIdx.x * blockDim.x + threadIdx.x) >> 5;
    const int lane = threadIdx.x & 31;

    const int j0 = idx[t * 3 + 0], j1 = idx[t * 3 + 1], j2 = idx[t * 3 + 2];
    float w0 = w[t * 3 + 0], w1 = w[t * 3 + 1], w2 = w[t * 3 + 2];
    const float inv = __fdividef(1.0f, w0 + w1 + w2);
    w0 *= inv; w1 *= inv; w2 *= inv;

    const float* r0 = xsrc + (size_t)j0 * C;
    const float* r1 = xsrc + (size_t)j1 * C;
    const float* r2 = xsrc + (size_t)j2 * C;
    float* orow = out + (size_t)t * LD;

    #pragma unroll
    for (int c = lane; c < C; c += 32)
        orow[c] = fmaf(w0, r0[c], fmaf(w1, r1[c], w2 * r2[c]));
    #pragma unroll
    for (int c = lane; c < CS; c += 32)
        orow[C + c] = xskip[(size_t)t * CS + c];
}

// -------- fused 2-layer MLP + par scale --------
// y = [tanh]( tanh(X @ Wa + ba) @ Wb + bb ) * p[batch]
// Block tile: 32 rows x H cols, 128 threads, thread tile 8 rows x (H/32) cols.
template<int LAYER>
__global__ __launch_bounds__(128) void gemm_fused_kernel(
    const float* __restrict__ Wa, const float* __restrict__ ba,
    const float* __restrict__ Wb, const float* __restrict__ bb,
    float* __restrict__ out_arg)
{
    constexpr int KD  = (LAYER == 1) ? KD1 : KD2;   // 384 / 192
    constexpr int H   = (LAYER == 1) ? H1  : H2;    // 256 / 128
    constexpr int O   = (LAYER == 1) ? O1  : O2;    // 128 / 64
    constexpr bool PLAIN = (LAYER == 2);
    constexpr int RPB = (LAYER == 1) ? N1 : N0;     // rows per batch
    constexpr int R   = 32;
    constexpr int CT1 = H / 32;                     // 8 / 4 cols per thread (phase 1)
    constexpr int CT2 = O / 32;                     // 4 / 2 cols per thread (phase 2)
    constexpr int RT  = R / 4;                      // 8 rows per thread

    extern __shared__ float smem[];
    float* xs = smem;            // R*KD
    float* hs = smem + R * KD;   // R*H

    const float* __restrict__ xin = (LAYER == 1) ? g_xcat1 : g_xcat2;
    float*       __restrict__ outp = (LAYER == 1) ? g_x1 : out_arg;
    const float* __restrict__ p   = (LAYER == 1) ? g_p0 : g_p1;

    const int tid = threadIdx.x;
    const int tx  = tid & 31;
    const int ty  = tid >> 5;                       // 0..3
    const int row0 = blockIdx.x * R;

    // Load 32 input rows (vectorized, coalesced, conflict-free STS)
    {
        const float4* src = reinterpret_cast<const float4*>(xin + (size_t)row0 * KD);
        float4* dst = reinterpret_cast<float4*>(xs);
        #pragma unroll
        for (int i = tid; i < R * KD / 4; i += 128) dst[i] = src[i];
    }
    __syncthreads();

    // ---- phase 1: H hidden units, tanh ----
    float acc[RT][CT1];
    #pragma unroll
    for (int r = 0; r < RT; r++)
        #pragma unroll
        for (int c = 0; c < CT1; c++) acc[r][c] = 0.0f;

    #pragma unroll 2
    for (int k = 0; k < KD; k++) {
        float wv[CT1];
        #pragma unroll
        for (int c = 0; c < CT1; c++) wv[c] = Wa[k * H + tx + 32 * c];
        #pragma unroll
        for (int r = 0; r < RT; r++) {
            float xv = xs[(ty * RT + r) * KD + k];   // warp-uniform broadcast
            #pragma unroll
            for (int c = 0; c < CT1; c++)
                acc[r][c] = fmaf(xv, wv[c], acc[r][c]);
        }
    }
    #pragma unroll
    for (int c = 0; c < CT1; c++) {
        float bj = ba[tx + 32 * c];
        #pragma unroll
        for (int r = 0; r < RT; r++)
            hs[(ty * RT + r) * H + tx + 32 * c] = ftanh(acc[r][c] + bj);
    }
    __syncthreads();

    // ---- phase 2: O outputs, optional tanh, * p ----
    float acc2[RT][CT2];
    #pragma unroll
    for (int r = 0; r < RT; r++)
        #pragma unroll
        for (int c = 0; c < CT2; c++) acc2[r][c] = 0.0f;

    #pragma unroll 2
    for (int k = 0; k < H; k++) {
        float wv[CT2];
        #pragma unroll
        for (int c = 0; c < CT2; c++) wv[c] = Wb[k * O + tx + 32 * c];
        #pragma unroll
        for (int r = 0; r < RT; r++) {
            float hv = hs[(ty * RT + r) * H + k];    // warp-uniform broadcast
            #pragma unroll
            for (int c = 0; c < CT2; c++)
                acc2[r][c] = fmaf(hv, wv[c], acc2[r][c]);
        }
    }

    const int bat = row0 / RPB;                      // block fully inside one batch
    #pragma unroll
    for (int c = 0; c < CT2; c++) {
        float bias = bb[tx + 32 * c];
        float pv   = p[bat * O + tx + 32 * c];
        #pragma unroll
        for (int r = 0; r < RT; r++) {
            float y = acc2[r][c] + bias;
            if (!PLAIN) y = ftanh(y);
            outp[(size_t)(row0 + ty * RT + r) * O + tx + 32 * c] = y * pv;
        }
    }
}

// -------- tail: append pos_skip_l0 and batch_skip_l0 (as float) --------
__global__ void tail_kernel(const float* __restrict__ pos0,
                            const int* __restrict__ bat0,
                            float* __restrict__ out)
{
    const int i = blockIdx.x * blockDim.x + threadIdx.x;
    const int NP = NT0 * 3;        // 98304
    if (i < NP)
        out[(size_t)NT0 * O2 + i] = pos0[i];
    else if (i < NP + NT0)
        out[(size_t)NT0 * O2 + i] = (float)bat0[i - NP];
}

extern "C" void kernel_launch(void* const* d_in, const int* in_sizes, int n_in,
                              void* d_out, int out_size) {
    const float* par          = (const float*)d_in[0];
    const float* x            = (const float*)d_in[1];
    const float* pos          = (const float*)d_in[2];
    // d_in[3] batch (unused: equal-size blocks)
    const float* x_skip_l1    = (const float*)d_in[4];
    const float* pos_skip_l1  = (const float*)d_in[5];
    // d_in[6] batch_skip_l1 (unused)
    const float* x_skip_l0    = (const float*)d_in[7];
    const float* pos_skip_l0  = (const float*)d_in[8];
    const int*   batch_skip_l0= (const int*)  d_in[9];
    const float* W0a = (const float*)d_in[10];
    const float* b0a = (const float*)d_in[11];
    const float* W0b = (const float*)d_in[12];
    const float* b0b = (const float*)d_in[13];
    const float* Wp0 = (const float*)d_in[14];
    const float* bp0 = (const float*)d_in[15];
    const float* W1a = (const float*)d_in[16];
    const float* b1a = (const float*)d_in[17];
    const float* W1b = (const float*)d_in[18];
    const float* b1b = (const float*)d_in[19];
    const float* Wp1 = (const float*)d_in[20];
    const float* bp1 = (const float*)d_in[21];
    float* out = (float*)d_out;

    const int smem1 = (32 * KD1 + 32 * H1) * sizeof(float);  // 81920
    const int smem2 = (32 * KD2 + 32 * H2) * sizeof(float);  // 40960
    cudaFuncSetAttribute(gemm_fused_kernel<1>, cudaFuncAttributeMaxDynamicSharedMemorySize, smem1);
    cudaFuncSetAttribute(gemm_fused_kernel<2>, cudaFuncAttributeMaxDynamicSharedMemorySize, smem2);

    par_kernel<<<1, 128>>>(par, Wp0, bp0, Wp1, bp1);

    // layer 1: interp x (N2 -> N1), MLP, par-scale
    knn_kernel<1><<<NT1 / 128, 128>>>(pos, pos_skip_l1);
    interp_concat_kernel<1><<<NT1 / 4, 128>>>(x, x_skip_l1);
    gemm_fused_kernel<1><<<NT1 / 32, 128, smem1>>>(W0a, b0a, W0b, b0b, nullptr);

    // layer 2: interp x1 (N1 -> N0), MLP, par-scale
    knn_kernel<2><<<NT0 / 128, 128>>>(pos_skip_l1, pos_skip_l0);
    interp_concat_kernel<2><<<NT0 / 4, 128>>>(nullptr, x_skip_l0);
    gemm_fused_kernel<2><<<NT0 / 32, 128, smem2>>>(W1a, b1a, W1b, b1b, out);

    // append pos + batch to output if the harness expects the full tuple
    const long long full = (long long)NT0 * O2 + (long long)NT0 * 3 + NT0;
    if ((long long)out_size >= full) {
        tail_kernel<<<(NT0 * 3 + NT0 + 255) / 256, 256>>>(pos_skip_l0, batch_skip_l0, out);
    }
}